// round 7
// baseline (speedup 1.0000x reference)
#include <cuda_runtime.h>
#include <cuda_fp16.h>
#include <cstdint>

// ---------------------------------------------------------------------------
// Problem constants
// ---------------------------------------------------------------------------
#define B_DIM 2048
#define C_DIM 32000
#define K_DIM 512

#define BM 128
#define BN 256
#define BK 64                    // 64 halves = 128 B per row per stage chunk
#define NCHUNK (K_DIM / BK)      // 8
#define STAGES 4

#define A_ROW_BYTES 128
#define A_STAGE_BYTES (BM * A_ROW_BYTES)     // 16384
#define B_STAGE_BYTES (BN * A_ROW_BYTES)     // 32768
#define STAGE_BYTES (A_STAGE_BYTES + B_STAGE_BYTES)  // 49152
#define DYN_SMEM (STAGES * STAGE_BYTES)      // 196608

// ---------------------------------------------------------------------------
// Scratch (normalized fp16 copies). Static __device__ => no allocs.
// ---------------------------------------------------------------------------
__device__ __half g_xn[(size_t)B_DIM * K_DIM];   // 2 MB
__device__ __half g_wn[(size_t)C_DIM * K_DIM];   // 32 MB

// ---------------------------------------------------------------------------
// Helpers (baseline PTX only — harness compiles for plain sm_103)
// ---------------------------------------------------------------------------
__device__ __forceinline__ uint32_t smem_u32(const void* p) {
    uint32_t a;
    asm("{ .reg .u64 t; cvta.to.shared.u64 t, %1; cvt.u32.u64 %0, t; }"
        : "=r"(a) : "l"(p));
    return a;
}

__device__ __forceinline__ void cp16(uint32_t s, const void* g) {
    asm volatile("cp.async.cg.shared.global [%0], [%1], 16;\n" :: "r"(s), "l"(g));
}
#define CP_COMMIT() asm volatile("cp.async.commit_group;" ::: "memory")

__device__ __forceinline__ void ldm_x4(uint32_t& r0, uint32_t& r1,
                                       uint32_t& r2, uint32_t& r3, uint32_t addr) {
    asm volatile("ldmatrix.sync.aligned.m8n8.x4.shared.b16 {%0,%1,%2,%3}, [%4];"
                 : "=r"(r0), "=r"(r1), "=r"(r2), "=r"(r3) : "r"(addr));
}

// m16n8k16 fp16 mma, fp32 accum
__device__ __forceinline__ void mma16(float* d,
                                      uint32_t a0, uint32_t a1, uint32_t a2, uint32_t a3,
                                      uint32_t b0, uint32_t b1) {
    asm volatile(
        "mma.sync.aligned.m16n8k16.row.col.f32.f16.f16.f32 "
        "{%0,%1,%2,%3}, {%4,%5,%6,%7}, {%8,%9}, {%0,%1,%2,%3};"
        : "+f"(d[0]), "+f"(d[1]), "+f"(d[2]), "+f"(d[3])
        : "r"(a0), "r"(a1), "r"(a2), "r"(a3), "r"(b0), "r"(b1));
}

// ---------------------------------------------------------------------------
// Kernel 1: per-row L2 normalize -> fp16, to scratch
// ---------------------------------------------------------------------------
__global__ void __launch_bounds__(128)
norm_kernel(const float* __restrict__ x, const float* __restrict__ w) {
    const int row = blockIdx.x;
    const float* src;
    __half* dst;
    if (row < B_DIM) {
        src = x + (size_t)row * K_DIM;
        dst = g_xn + (size_t)row * K_DIM;
    } else {
        const int r = row - B_DIM;
        src = w + (size_t)r * K_DIM;
        dst = g_wn + (size_t)r * K_DIM;
    }
    const int t = threadIdx.x;
    float4 v = reinterpret_cast<const float4*>(src)[t];
    float ss = v.x * v.x + v.y * v.y + v.z * v.z + v.w * v.w;
    #pragma unroll
    for (int o = 16; o > 0; o >>= 1) ss += __shfl_xor_sync(0xffffffffu, ss, o);
    __shared__ float red[4];
    if ((t & 31) == 0) red[t >> 5] = ss;
    __syncthreads();
    const float tot = red[0] + red[1] + red[2] + red[3];
    const float scale = 1.0f / fmaxf(sqrtf(tot), 1e-12f);
    __half2 h0 = __floats2half2_rn(v.x * scale, v.y * scale);
    __half2 h1 = __floats2half2_rn(v.z * scale, v.w * scale);
    uint2 o2 = make_uint2(*reinterpret_cast<uint32_t*>(&h0),
                          *reinterpret_cast<uint32_t*>(&h1));
    reinterpret_cast<uint2*>(dst)[t] = o2;
}

// ---------------------------------------------------------------------------
// Kernel 2: fp16 mma.sync GEMM, CTA 128x256, warp 64x64, 4-stage cp.async
// Swizzle: 16B chunk m of row r stored at slot m ^ (r & 7).
// ---------------------------------------------------------------------------
__device__ __forceinline__ void load_stage(int stage, int kc, int tid, uint32_t smem_u,
                                           const __half* __restrict__ gA,
                                           const __half* __restrict__ gB) {
    const int k0 = kc * BK;
    const uint32_t baseA = smem_u + (uint32_t)stage * STAGE_BYTES;
    const uint32_t baseB = baseA + A_STAGE_BYTES;
    #pragma unroll
    for (int i = 0; i < 4; i++) {        // A: 1024 chunks of 16B
        const int idx = tid + i * 256;
        const int r = idx >> 3, m = idx & 7;
        const uint32_t slot = (uint32_t)(m ^ (r & 7));
        cp16(baseA + (uint32_t)(r * 8 + slot) * 16u,
             gA + (size_t)r * K_DIM + k0 + m * 8);
    }
    #pragma unroll
    for (int i = 0; i < 8; i++) {        // B: 2048 chunks of 16B
        const int idx = tid + i * 256;
        const int r = idx >> 3, m = idx & 7;
        const uint32_t slot = (uint32_t)(m ^ (r & 7));
        cp16(baseB + (uint32_t)(r * 8 + slot) * 16u,
             gB + (size_t)r * K_DIM + k0 + m * 8);
    }
}

__global__ void __launch_bounds__(256, 1)
gemm_kernel(float* __restrict__ out_loss, float* __restrict__ out_pred,
            const int* __restrict__ tg) {
    extern __shared__ char dyn_smem[];
    const uint32_t smem_u = smem_u32(dyn_smem);
    const int tid = threadIdx.x;

    const int m_base = blockIdx.x * BM;    // gridDim.x = 16
    const int n_base = blockIdx.y * BN;    // gridDim.y = 125
    const __half* gA = g_xn + (size_t)m_base * K_DIM;
    const __half* gB = g_wn + (size_t)n_base * K_DIM;

    const int wid = tid >> 5;
    const int warp_m = wid & 1;            // 2 warps in M
    const int warp_n = wid >> 1;           // 4 warps in N
    const int lane = tid & 31;
    const int c = lane & 3;
    const int quad = lane >> 2;

    __shared__ int s_tg[BM];
    if (tid < BM) s_tg[tid] = tg[m_base + tid];

    float acc[4][8][4];
    #pragma unroll
    for (int t = 0; t < 4; t++)
        #pragma unroll
        for (int u = 0; u < 8; u++)
            #pragma unroll
            for (int e = 0; e < 4; e++) acc[t][u][e] = 0.0f;

    // ldmatrix lane-address components
    const int sel = lane >> 3;             // matrix index 0..3
    const int rw = lane & 7;               // row within 8x8 matrix
    // A: mat0=(m0,k0) mat1=(m+8,k0) mat2=(m0,k+8) mat3=(m+8,k+8)
    const int a_moff = (sel & 1) * 8;
    const int a_koff = sel >> 1;           // extra 16B chunk
    // B: mat0=(n0,k0) mat1=(n0,k+8) mat2=(n+8,k0) mat3=(n+8,k+8)
    const int b_noff = (sel >> 1) * 8;
    const int b_koff = sel & 1;

    // Prologue
    #pragma unroll
    for (int s = 0; s < STAGES - 1; s++) {
        load_stage(s, s, tid, smem_u, gA, gB);
        CP_COMMIT();
    }

    #pragma unroll 1
    for (int kc = 0; kc < NCHUNK; kc++) {
        asm volatile("cp.async.wait_group %0;" :: "n"(STAGES - 2));
        __syncthreads();   // stage kc visible; all warps past compute of kc-1

        const int j = kc + STAGES - 1;
        if (j < NCHUNK) load_stage(j & (STAGES - 1), j, tid, smem_u, gA, gB);
        CP_COMMIT();

        const uint32_t baseA = smem_u + (uint32_t)(kc & (STAGES - 1)) * STAGE_BYTES;
        const uint32_t baseB = baseA + A_STAGE_BYTES;

        #pragma unroll
        for (int g = 0; g < 4; g++) {      // 4 k16 groups per stage
            uint32_t bf[8][2];
            #pragma unroll
            for (int p = 0; p < 4; p++) {  // 4 n16 blocks -> 8 n8 fragments
                const int nrow = warp_n * 64 + p * 16 + b_noff + rw;
                const uint32_t slot = (uint32_t)((g * 2 + b_koff) ^ (nrow & 7));
                uint32_t r0, r1, r2, r3;
                ldm_x4(r0, r1, r2, r3, baseB + (uint32_t)nrow * 128u + slot * 16u);
                bf[2 * p][0] = r0; bf[2 * p][1] = r1;
                bf[2 * p + 1][0] = r2; bf[2 * p + 1][1] = r3;
            }
            #pragma unroll
            for (int t = 0; t < 4; t++) {
                const int mrow = warp_m * 64 + t * 16 + a_moff + rw;
                const uint32_t slot = (uint32_t)((g * 2 + a_koff) ^ (mrow & 7));
                uint32_t a0, a1, a2, a3;
                ldm_x4(a0, a1, a2, a3, baseA + (uint32_t)mrow * 128u + slot * 16u);
                #pragma unroll
                for (int u = 0; u < 8; u++)
                    mma16(acc[t][u], a0, a1, a2, a3, bf[u][0], bf[u][1]);
            }
        }
    }
    __syncthreads();

    // ---- Epilogue: regs -> SMEM (pitch 264) -> coalesced STG.128 x2 ----
    float* sE = reinterpret_cast<float*>(dyn_smem);
    #pragma unroll
    for (int t = 0; t < 4; t++) {
        const int row = warp_m * 64 + t * 16 + quad;
        #pragma unroll
        for (int u = 0; u < 8; u++) {
            const int col = warp_n * 64 + u * 8 + c * 2;
            float2 v0 = make_float2(acc[t][u][0] * 32.0f, acc[t][u][1] * 32.0f);
            float2 v1 = make_float2(acc[t][u][2] * 32.0f, acc[t][u][3] * 32.0f);
            *reinterpret_cast<float2*>(&sE[(size_t)row * 264 + col]) = v0;
            *reinterpret_cast<float2*>(&sE[(size_t)(row + 8) * 264 + col]) = v1;
        }
    }
    __syncthreads();

    #pragma unroll 4
    for (int i = 0; i < 32; i++) {
        const int linear = tid + i * 256;           // 8192 float4s total
        const int rr = linear >> 6;                 // row 0..127
        const int c4 = linear & 63;                 // float4 col 0..63
        const float4 v = *reinterpret_cast<const float4*>(&sE[(size_t)rr * 264 + c4 * 4]);
        const size_t gidx = (size_t)(m_base + rr) * C_DIM + (size_t)(n_base + c4 * 4);
        *reinterpret_cast<float4*>(&out_pred[gidx]) = v;
        // fused margin fixup on the loss copy
        float4 v2 = v;
        const int d = s_tg[rr] - (n_base + c4 * 4);
        if ((unsigned)d < 4u) reinterpret_cast<float*>(&v2)[d] -= 16.0f;
        *reinterpret_cast<float4*>(&out_loss[gidx]) = v2;
    }
}

// ---------------------------------------------------------------------------
// Launch
// ---------------------------------------------------------------------------
extern "C" void kernel_launch(void* const* d_in, const int* in_sizes, int n_in,
                              void* d_out, int out_size) {
    const float* x = (const float*)d_in[0];
    const float* w = (const float*)d_in[1];
    const int* tg = (const int*)d_in[2];

    float* out_loss = (float*)d_out;                          // tuple elem 0
    float* out_pred = out_loss + (size_t)B_DIM * C_DIM;       // tuple elem 1

    norm_kernel<<<B_DIM + C_DIM, 128>>>(x, w);

    cudaFuncSetAttribute(gemm_kernel, cudaFuncAttributeMaxDynamicSharedMemorySize,
                         DYN_SMEM);
    gemm_kernel<<<dim3(B_DIM / BM, C_DIM / BN), 256, DYN_SMEM>>>(out_loss, out_pred, tg);
}

// round 8
// speedup vs baseline: 1.0019x; 1.0019x over previous
#include <cuda_runtime.h>
#include <cuda_fp16.h>
#include <cstdint>

// ---------------------------------------------------------------------------
// Problem constants
// ---------------------------------------------------------------------------
#define B_DIM 2048
#define C_DIM 32000
#define K_DIM 512

#define BM 128
#define BN 256
#define BK 64                    // 64 halves = 128 B per row per stage chunk
#define NCHUNK (K_DIM / BK)      // 8
#define STAGES 4

#define A_ROW_BYTES 128
#define A_STAGE_BYTES (BM * A_ROW_BYTES)     // 16384
#define B_STAGE_BYTES (BN * A_ROW_BYTES)     // 32768
#define STAGE_BYTES (A_STAGE_BYTES + B_STAGE_BYTES)  // 49152
#define DYN_SMEM (STAGES * STAGE_BYTES)      // 196608

// ---------------------------------------------------------------------------
// Scratch (normalized fp16 copies). Static __device__ => no allocs.
// ---------------------------------------------------------------------------
__device__ __half g_xn[(size_t)B_DIM * K_DIM];   // 2 MB
__device__ __half g_wn[(size_t)C_DIM * K_DIM];   // 32 MB

// ---------------------------------------------------------------------------
// Helpers (baseline PTX only — harness compiles for plain sm_103)
// ---------------------------------------------------------------------------
__device__ __forceinline__ uint32_t smem_u32(const void* p) {
    uint32_t a;
    asm("{ .reg .u64 t; cvta.to.shared.u64 t, %1; cvt.u32.u64 %0, t; }"
        : "=r"(a) : "l"(p));
    return a;
}

__device__ __forceinline__ void cp16(uint32_t s, const void* g) {
    asm volatile("cp.async.cg.shared.global [%0], [%1], 16;\n" :: "r"(s), "l"(g));
}
#define CP_COMMIT() asm volatile("cp.async.commit_group;" ::: "memory")

__device__ __forceinline__ void ldm_x4(uint32_t& r0, uint32_t& r1,
                                       uint32_t& r2, uint32_t& r3, uint32_t addr) {
    asm volatile("ldmatrix.sync.aligned.m8n8.x4.shared.b16 {%0,%1,%2,%3}, [%4];"
                 : "=r"(r0), "=r"(r1), "=r"(r2), "=r"(r3) : "r"(addr));
}

// m16n8k16 fp16 mma, fp32 accum
__device__ __forceinline__ void mma16(float* d,
                                      uint32_t a0, uint32_t a1, uint32_t a2, uint32_t a3,
                                      uint32_t b0, uint32_t b1) {
    asm volatile(
        "mma.sync.aligned.m16n8k16.row.col.f32.f16.f16.f32 "
        "{%0,%1,%2,%3}, {%4,%5,%6,%7}, {%8,%9}, {%0,%1,%2,%3};"
        : "+f"(d[0]), "+f"(d[1]), "+f"(d[2]), "+f"(d[3])
        : "r"(a0), "r"(a1), "r"(a2), "r"(a3), "r"(b0), "r"(b1));
}

// ---------------------------------------------------------------------------
// Kernel 1: per-row L2 normalize -> fp16, to scratch
// ---------------------------------------------------------------------------
__global__ void __launch_bounds__(128)
norm_kernel(const float* __restrict__ x, const float* __restrict__ w) {
    const int row = blockIdx.x;
    const float* src;
    __half* dst;
    if (row < B_DIM) {
        src = x + (size_t)row * K_DIM;
        dst = g_xn + (size_t)row * K_DIM;
    } else {
        const int r = row - B_DIM;
        src = w + (size_t)r * K_DIM;
        dst = g_wn + (size_t)r * K_DIM;
    }
    const int t = threadIdx.x;
    float4 v = reinterpret_cast<const float4*>(src)[t];
    float ss = v.x * v.x + v.y * v.y + v.z * v.z + v.w * v.w;
    #pragma unroll
    for (int o = 16; o > 0; o >>= 1) ss += __shfl_xor_sync(0xffffffffu, ss, o);
    __shared__ float red[4];
    if ((t & 31) == 0) red[t >> 5] = ss;
    __syncthreads();
    const float tot = red[0] + red[1] + red[2] + red[3];
    const float scale = 1.0f / fmaxf(sqrtf(tot), 1e-12f);
    __half2 h0 = __floats2half2_rn(v.x * scale, v.y * scale);
    __half2 h1 = __floats2half2_rn(v.z * scale, v.w * scale);
    uint2 o2 = make_uint2(*reinterpret_cast<uint32_t*>(&h0),
                          *reinterpret_cast<uint32_t*>(&h1));
    reinterpret_cast<uint2*>(dst)[t] = o2;
}

// ---------------------------------------------------------------------------
// Kernel 2: fp16 mma.sync GEMM, CTA 128x256, warp 64x64, 4-stage cp.async
// Swizzle: 16B chunk m of row r stored at slot m ^ (r & 7).
// ---------------------------------------------------------------------------
__device__ __forceinline__ void load_stage(int stage, int kc, int tid, uint32_t smem_u,
                                           const __half* __restrict__ gA,
                                           const __half* __restrict__ gB) {
    const int k0 = kc * BK;
    const uint32_t baseA = smem_u + (uint32_t)stage * STAGE_BYTES;
    const uint32_t baseB = baseA + A_STAGE_BYTES;
    #pragma unroll
    for (int i = 0; i < 4; i++) {        // A: 1024 chunks of 16B
        const int idx = tid + i * 256;
        const int r = idx >> 3, m = idx & 7;
        const uint32_t slot = (uint32_t)(m ^ (r & 7));
        cp16(baseA + (uint32_t)(r * 8 + slot) * 16u,
             gA + (size_t)r * K_DIM + k0 + m * 8);
    }
    #pragma unroll
    for (int i = 0; i < 8; i++) {        // B: 2048 chunks of 16B
        const int idx = tid + i * 256;
        const int r = idx >> 3, m = idx & 7;
        const uint32_t slot = (uint32_t)(m ^ (r & 7));
        cp16(baseB + (uint32_t)(r * 8 + slot) * 16u,
             gB + (size_t)r * K_DIM + k0 + m * 8);
    }
}

__global__ void __launch_bounds__(256, 1)
gemm_kernel(float* __restrict__ out_loss, float* __restrict__ out_pred,
            const int* __restrict__ tg) {
    extern __shared__ char dyn_smem[];
    const uint32_t smem_u = smem_u32(dyn_smem);
    const int tid = threadIdx.x;

    const int m_base = blockIdx.x * BM;    // gridDim.x = 16
    const int n_base = blockIdx.y * BN;    // gridDim.y = 125
    const __half* gA = g_xn + (size_t)m_base * K_DIM;
    const __half* gB = g_wn + (size_t)n_base * K_DIM;

    const int wid = tid >> 5;
    const int warp_m = wid & 1;            // 2 warps in M
    const int warp_n = wid >> 1;           // 4 warps in N
    const int lane = tid & 31;
    const int c = lane & 3;
    const int quad = lane >> 2;

    __shared__ int s_tg[BM];
    if (tid < BM) s_tg[tid] = tg[m_base + tid];

    float acc[4][8][4];
    #pragma unroll
    for (int t = 0; t < 4; t++)
        #pragma unroll
        for (int u = 0; u < 8; u++)
            #pragma unroll
            for (int e = 0; e < 4; e++) acc[t][u][e] = 0.0f;

    // ldmatrix lane-address components
    const int sel = lane >> 3;             // matrix index 0..3
    const int rw = lane & 7;               // row within 8x8 matrix
    // A: mat0=(m0,k0) mat1=(m+8,k0) mat2=(m0,k+8) mat3=(m+8,k+8)
    const int a_moff = (sel & 1) * 8;
    const int a_koff = sel >> 1;           // extra 16B chunk
    // B: mat0=(n0,k0) mat1=(n0,k+8) mat2=(n+8,k0) mat3=(n+8,k+8)
    const int b_noff = (sel >> 1) * 8;
    const int b_koff = sel & 1;

    // Prologue
    #pragma unroll
    for (int s = 0; s < STAGES - 1; s++) {
        load_stage(s, s, tid, smem_u, gA, gB);
        CP_COMMIT();
    }

    #pragma unroll 1
    for (int kc = 0; kc < NCHUNK; kc++) {
        asm volatile("cp.async.wait_group %0;" :: "n"(STAGES - 2));
        __syncthreads();   // stage kc visible; all warps past compute of kc-1

        const int j = kc + STAGES - 1;
        if (j < NCHUNK) load_stage(j & (STAGES - 1), j, tid, smem_u, gA, gB);
        CP_COMMIT();

        const uint32_t baseA = smem_u + (uint32_t)(kc & (STAGES - 1)) * STAGE_BYTES;
        const uint32_t baseB = baseA + A_STAGE_BYTES;

        #pragma unroll
        for (int g = 0; g < 4; g++) {      // 4 k16 groups per stage
            uint32_t bf[8][2];
            #pragma unroll
            for (int p = 0; p < 4; p++) {  // 4 n16 blocks -> 8 n8 fragments
                const int nrow = warp_n * 64 + p * 16 + b_noff + rw;
                const uint32_t slot = (uint32_t)((g * 2 + b_koff) ^ (nrow & 7));
                uint32_t r0, r1, r2, r3;
                ldm_x4(r0, r1, r2, r3, baseB + (uint32_t)nrow * 128u + slot * 16u);
                bf[2 * p][0] = r0; bf[2 * p][1] = r1;
                bf[2 * p + 1][0] = r2; bf[2 * p + 1][1] = r3;
            }
            #pragma unroll
            for (int t = 0; t < 4; t++) {
                const int mrow = warp_m * 64 + t * 16 + a_moff + rw;
                const uint32_t slot = (uint32_t)((g * 2 + a_koff) ^ (mrow & 7));
                uint32_t a0, a1, a2, a3;
                ldm_x4(a0, a1, a2, a3, baseA + (uint32_t)mrow * 128u + slot * 16u);
                #pragma unroll
                for (int u = 0; u < 8; u++)
                    mma16(acc[t][u], a0, a1, a2, a3, bf[u][0], bf[u][1]);
            }
        }
    }
    __syncthreads();

    // ---- Epilogue: regs -> SMEM (pitch 264) -> coalesced STG.128 x2 ----
    float* sE = reinterpret_cast<float*>(dyn_smem);
    #pragma unroll
    for (int t = 0; t < 4; t++) {
        const int row = warp_m * 64 + t * 16 + quad;
        #pragma unroll
        for (int u = 0; u < 8; u++) {
            const int col = warp_n * 64 + u * 8 + c * 2;
            float2 v0 = make_float2(acc[t][u][0] * 32.0f, acc[t][u][1] * 32.0f);
            float2 v1 = make_float2(acc[t][u][2] * 32.0f, acc[t][u][3] * 32.0f);
            *reinterpret_cast<float2*>(&sE[(size_t)row * 264 + col]) = v0;
            *reinterpret_cast<float2*>(&sE[(size_t)(row + 8) * 264 + col]) = v1;
        }
    }
    __syncthreads();

    #pragma unroll 4
    for (int i = 0; i < 32; i++) {
        const int linear = tid + i * 256;           // 8192 float4s total
        const int rr = linear >> 6;                 // row 0..127
        const int c4 = linear & 63;                 // float4 col 0..63
        const float4 v = *reinterpret_cast<const float4*>(&sE[(size_t)rr * 264 + c4 * 4]);
        const size_t gidx = (size_t)(m_base + rr) * C_DIM + (size_t)(n_base + c4 * 4);
        *reinterpret_cast<float4*>(&out_pred[gidx]) = v;
        // fused margin fixup on the loss copy
        float4 v2 = v;
        const int d = s_tg[rr] - (n_base + c4 * 4);
        if ((unsigned)d < 4u) reinterpret_cast<float*>(&v2)[d] -= 16.0f;
        *reinterpret_cast<float4*>(&out_loss[gidx]) = v2;
    }
}

// ---------------------------------------------------------------------------
// Launch
// ---------------------------------------------------------------------------
extern "C" void kernel_launch(void* const* d_in, const int* in_sizes, int n_in,
                              void* d_out, int out_size) {
    const float* x = (const float*)d_in[0];
    const float* w = (const float*)d_in[1];
    const int* tg = (const int*)d_in[2];

    float* out_loss = (float*)d_out;                          // tuple elem 0
    float* out_pred = out_loss + (size_t)B_DIM * C_DIM;       // tuple elem 1

    norm_kernel<<<B_DIM + C_DIM, 128>>>(x, w);

    cudaFuncSetAttribute(gemm_kernel, cudaFuncAttributeMaxDynamicSharedMemorySize,
                         DYN_SMEM);
    gemm_kernel<<<dim3(B_DIM / BM, C_DIM / BN), 256, DYN_SMEM>>>(out_loss, out_pred, tg);
}

// round 9
// speedup vs baseline: 1.0024x; 1.0004x over previous
#include <cuda_runtime.h>
#include <cuda_fp16.h>
#include <cstdint>

// ---------------------------------------------------------------------------
// Problem constants
// ---------------------------------------------------------------------------
#define B_DIM 2048
#define C_DIM 32000
#define K_DIM 512

#define BM 128
#define BN 256
#define BK 64                    // 64 halves = 128 B per row per stage chunk
#define NCHUNK (K_DIM / BK)      // 8
#define STAGES 4

#define A_ROW_BYTES 128
#define A_STAGE_BYTES (BM * A_ROW_BYTES)     // 16384
#define B_STAGE_BYTES (BN * A_ROW_BYTES)     // 32768
#define STAGE_BYTES (A_STAGE_BYTES + B_STAGE_BYTES)  // 49152
#define DYN_SMEM (STAGES * STAGE_BYTES)      // 196608

// ---------------------------------------------------------------------------
// Scratch (normalized fp16 copies). Static __device__ => no allocs.
// ---------------------------------------------------------------------------
__device__ __half g_xn[(size_t)B_DIM * K_DIM];   // 2 MB
__device__ __half g_wn[(size_t)C_DIM * K_DIM];   // 32 MB

// ---------------------------------------------------------------------------
// Helpers (baseline PTX only — harness compiles for plain sm_103)
// ---------------------------------------------------------------------------
__device__ __forceinline__ uint32_t smem_u32(const void* p) {
    uint32_t a;
    asm("{ .reg .u64 t; cvta.to.shared.u64 t, %1; cvt.u32.u64 %0, t; }"
        : "=r"(a) : "l"(p));
    return a;
}

__device__ __forceinline__ void cp16(uint32_t s, const void* g) {
    asm volatile("cp.async.cg.shared.global [%0], [%1], 16;\n" :: "r"(s), "l"(g));
}
#define CP_COMMIT() asm volatile("cp.async.commit_group;" ::: "memory")

__device__ __forceinline__ void ldm_x4(uint32_t& r0, uint32_t& r1,
                                       uint32_t& r2, uint32_t& r3, uint32_t addr) {
    asm volatile("ldmatrix.sync.aligned.m8n8.x4.shared.b16 {%0,%1,%2,%3}, [%4];"
                 : "=r"(r0), "=r"(r1), "=r"(r2), "=r"(r3) : "r"(addr));
}

// m16n8k16 fp16 mma, fp32 accum
__device__ __forceinline__ void mma16(float* d,
                                      uint32_t a0, uint32_t a1, uint32_t a2, uint32_t a3,
                                      uint32_t b0, uint32_t b1) {
    asm volatile(
        "mma.sync.aligned.m16n8k16.row.col.f32.f16.f16.f32 "
        "{%0,%1,%2,%3}, {%4,%5,%6,%7}, {%8,%9}, {%0,%1,%2,%3};"
        : "+f"(d[0]), "+f"(d[1]), "+f"(d[2]), "+f"(d[3])
        : "r"(a0), "r"(a1), "r"(a2), "r"(a3), "r"(b0), "r"(b1));
}

// ---------------------------------------------------------------------------
// Kernel 1: per-row L2 normalize -> fp16, to scratch
// ---------------------------------------------------------------------------
__global__ void __launch_bounds__(128)
norm_kernel(const float* __restrict__ x, const float* __restrict__ w) {
    const int row = blockIdx.x;
    const float* src;
    __half* dst;
    if (row < B_DIM) {
        src = x + (size_t)row * K_DIM;
        dst = g_xn + (size_t)row * K_DIM;
    } else {
        const int r = row - B_DIM;
        src = w + (size_t)r * K_DIM;
        dst = g_wn + (size_t)r * K_DIM;
    }
    const int t = threadIdx.x;
    float4 v = reinterpret_cast<const float4*>(src)[t];
    float ss = v.x * v.x + v.y * v.y + v.z * v.z + v.w * v.w;
    #pragma unroll
    for (int o = 16; o > 0; o >>= 1) ss += __shfl_xor_sync(0xffffffffu, ss, o);
    __shared__ float red[4];
    if ((t & 31) == 0) red[t >> 5] = ss;
    __syncthreads();
    const float tot = red[0] + red[1] + red[2] + red[3];
    const float scale = 1.0f / fmaxf(sqrtf(tot), 1e-12f);
    __half2 h0 = __floats2half2_rn(v.x * scale, v.y * scale);
    __half2 h1 = __floats2half2_rn(v.z * scale, v.w * scale);
    uint2 o2 = make_uint2(*reinterpret_cast<uint32_t*>(&h0),
                          *reinterpret_cast<uint32_t*>(&h1));
    reinterpret_cast<uint2*>(dst)[t] = o2;
}

// ---------------------------------------------------------------------------
// Kernel 2: fp16 mma.sync GEMM, CTA 128x256, warp 64x64, 4-stage cp.async
// Swizzle: 16B chunk m of row r stored at slot m ^ (r & 7).
// ---------------------------------------------------------------------------
__device__ __forceinline__ void load_stage(int stage, int kc, int tid, uint32_t smem_u,
                                           const __half* __restrict__ gA,
                                           const __half* __restrict__ gB) {
    const int k0 = kc * BK;
    const uint32_t baseA = smem_u + (uint32_t)stage * STAGE_BYTES;
    const uint32_t baseB = baseA + A_STAGE_BYTES;
    #pragma unroll
    for (int i = 0; i < 4; i++) {        // A: 1024 chunks of 16B
        const int idx = tid + i * 256;
        const int r = idx >> 3, m = idx & 7;
        const uint32_t slot = (uint32_t)(m ^ (r & 7));
        cp16(baseA + (uint32_t)(r * 8 + slot) * 16u,
             gA + (size_t)r * K_DIM + k0 + m * 8);
    }
    #pragma unroll
    for (int i = 0; i < 8; i++) {        // B: 2048 chunks of 16B
        const int idx = tid + i * 256;
        const int r = idx >> 3, m = idx & 7;
        const uint32_t slot = (uint32_t)(m ^ (r & 7));
        cp16(baseB + (uint32_t)(r * 8 + slot) * 16u,
             gB + (size_t)r * K_DIM + k0 + m * 8);
    }
}

__global__ void __launch_bounds__(256, 1)
gemm_kernel(float* __restrict__ out_loss, float* __restrict__ out_pred,
            const int* __restrict__ tg) {
    extern __shared__ char dyn_smem[];
    const uint32_t smem_u = smem_u32(dyn_smem);
    const int tid = threadIdx.x;

    const int m_base = blockIdx.x * BM;    // gridDim.x = 16
    const int n_base = blockIdx.y * BN;    // gridDim.y = 125
    const __half* gA = g_xn + (size_t)m_base * K_DIM;
    const __half* gB = g_wn + (size_t)n_base * K_DIM;

    const int wid = tid >> 5;
    const int warp_m = wid & 1;            // 2 warps in M
    const int warp_n = wid >> 1;           // 4 warps in N
    const int lane = tid & 31;
    const int c = lane & 3;
    const int quad = lane >> 2;

    __shared__ int s_tg[BM];
    if (tid < BM) s_tg[tid] = tg[m_base + tid];

    float acc[4][8][4];
    #pragma unroll
    for (int t = 0; t < 4; t++)
        #pragma unroll
        for (int u = 0; u < 8; u++)
            #pragma unroll
            for (int e = 0; e < 4; e++) acc[t][u][e] = 0.0f;

    // ldmatrix lane-address components
    const int sel = lane >> 3;             // matrix index 0..3
    const int rw = lane & 7;               // row within 8x8 matrix
    // A: mat0=(m0,k0) mat1=(m+8,k0) mat2=(m0,k+8) mat3=(m+8,k+8)
    const int a_moff = (sel & 1) * 8;
    const int a_koff = sel >> 1;           // extra 16B chunk
    // B: mat0=(n0,k0) mat1=(n0,k+8) mat2=(n+8,k0) mat3=(n+8,k+8)
    const int b_noff = (sel >> 1) * 8;
    const int b_koff = sel & 1;

    // Prologue
    #pragma unroll
    for (int s = 0; s < STAGES - 1; s++) {
        load_stage(s, s, tid, smem_u, gA, gB);
        CP_COMMIT();
    }

    #pragma unroll 1
    for (int kc = 0; kc < NCHUNK; kc++) {
        asm volatile("cp.async.wait_group %0;" :: "n"(STAGES - 2));
        __syncthreads();   // stage kc visible; all warps past compute of kc-1

        const int j = kc + STAGES - 1;
        if (j < NCHUNK) load_stage(j & (STAGES - 1), j, tid, smem_u, gA, gB);
        CP_COMMIT();

        const uint32_t baseA = smem_u + (uint32_t)(kc & (STAGES - 1)) * STAGE_BYTES;
        const uint32_t baseB = baseA + A_STAGE_BYTES;

        #pragma unroll
        for (int g = 0; g < 4; g++) {      // 4 k16 groups per stage
            uint32_t bf[8][2];
            #pragma unroll
            for (int p = 0; p < 4; p++) {  // 4 n16 blocks -> 8 n8 fragments
                const int nrow = warp_n * 64 + p * 16 + b_noff + rw;
                const uint32_t slot = (uint32_t)((g * 2 + b_koff) ^ (nrow & 7));
                uint32_t r0, r1, r2, r3;
                ldm_x4(r0, r1, r2, r3, baseB + (uint32_t)nrow * 128u + slot * 16u);
                bf[2 * p][0] = r0; bf[2 * p][1] = r1;
                bf[2 * p + 1][0] = r2; bf[2 * p + 1][1] = r3;
            }
            #pragma unroll
            for (int t = 0; t < 4; t++) {
                const int mrow = warp_m * 64 + t * 16 + a_moff + rw;
                const uint32_t slot = (uint32_t)((g * 2 + a_koff) ^ (mrow & 7));
                uint32_t a0, a1, a2, a3;
                ldm_x4(a0, a1, a2, a3, baseA + (uint32_t)mrow * 128u + slot * 16u);
                #pragma unroll
                for (int u = 0; u < 8; u++)
                    mma16(acc[t][u], a0, a1, a2, a3, bf[u][0], bf[u][1]);
            }
        }
    }
    __syncthreads();

    // ---- Epilogue: regs -> SMEM (pitch 264) -> coalesced STG.128 x2 ----
    float* sE = reinterpret_cast<float*>(dyn_smem);
    #pragma unroll
    for (int t = 0; t < 4; t++) {
        const int row = warp_m * 64 + t * 16 + quad;
        #pragma unroll
        for (int u = 0; u < 8; u++) {
            const int col = warp_n * 64 + u * 8 + c * 2;
            float2 v0 = make_float2(acc[t][u][0] * 32.0f, acc[t][u][1] * 32.0f);
            float2 v1 = make_float2(acc[t][u][2] * 32.0f, acc[t][u][3] * 32.0f);
            *reinterpret_cast<float2*>(&sE[(size_t)row * 264 + col]) = v0;
            *reinterpret_cast<float2*>(&sE[(size_t)(row + 8) * 264 + col]) = v1;
        }
    }
    __syncthreads();

    #pragma unroll 4
    for (int i = 0; i < 32; i++) {
        const int linear = tid + i * 256;           // 8192 float4s total
        const int rr = linear >> 6;                 // row 0..127
        const int c4 = linear & 63;                 // float4 col 0..63
        const float4 v = *reinterpret_cast<const float4*>(&sE[(size_t)rr * 264 + c4 * 4]);
        const size_t gidx = (size_t)(m_base + rr) * C_DIM + (size_t)(n_base + c4 * 4);
        *reinterpret_cast<float4*>(&out_pred[gidx]) = v;
        // fused margin fixup on the loss copy
        float4 v2 = v;
        const int d = s_tg[rr] - (n_base + c4 * 4);
        if ((unsigned)d < 4u) reinterpret_cast<float*>(&v2)[d] -= 16.0f;
        *reinterpret_cast<float4*>(&out_loss[gidx]) = v2;
    }
}

// ---------------------------------------------------------------------------
// Launch
// ---------------------------------------------------------------------------
extern "C" void kernel_launch(void* const* d_in, const int* in_sizes, int n_in,
                              void* d_out, int out_size) {
    const float* x = (const float*)d_in[0];
    const float* w = (const float*)d_in[1];
    const int* tg = (const int*)d_in[2];

    float* out_loss = (float*)d_out;                          // tuple elem 0
    float* out_pred = out_loss + (size_t)B_DIM * C_DIM;       // tuple elem 1

    norm_kernel<<<B_DIM + C_DIM, 128>>>(x, w);

    cudaFuncSetAttribute(gemm_kernel, cudaFuncAttributeMaxDynamicSharedMemorySize,
                         DYN_SMEM);
    gemm_kernel<<<dim3(B_DIM / BM, C_DIM / BN), 256, DYN_SMEM>>>(out_loss, out_pred, tg);
}

// round 10
// speedup vs baseline: 1.0051x; 1.0027x over previous
#include <cuda_runtime.h>
#include <cuda_fp16.h>
#include <cstdint>

// ---------------------------------------------------------------------------
// Problem constants
// ---------------------------------------------------------------------------
#define B_DIM 2048
#define C_DIM 32000
#define K_DIM 512

#define BM 128
#define BN 256
#define BK 64                    // 64 halves = 128 B per row per stage chunk
#define NCHUNK (K_DIM / BK)      // 8
#define STAGES 4

#define A_ROW_BYTES 128
#define A_STAGE_BYTES (BM * A_ROW_BYTES)     // 16384
#define B_STAGE_BYTES (BN * A_ROW_BYTES)     // 32768
#define STAGE_BYTES (A_STAGE_BYTES + B_STAGE_BYTES)  // 49152
#define DYN_SMEM (STAGES * STAGE_BYTES)      // 196608

// ---------------------------------------------------------------------------
// Scratch (normalized fp16 copies). Static __device__ => no allocs.
// ---------------------------------------------------------------------------
__device__ __half g_xn[(size_t)B_DIM * K_DIM];   // 2 MB
__device__ __half g_wn[(size_t)C_DIM * K_DIM];   // 32 MB

// ---------------------------------------------------------------------------
// Helpers (baseline PTX only — harness compiles for plain sm_103)
// ---------------------------------------------------------------------------
__device__ __forceinline__ uint32_t smem_u32(const void* p) {
    uint32_t a;
    asm("{ .reg .u64 t; cvta.to.shared.u64 t, %1; cvt.u32.u64 %0, t; }"
        : "=r"(a) : "l"(p));
    return a;
}

__device__ __forceinline__ void cp16(uint32_t s, const void* g) {
    asm volatile("cp.async.cg.shared.global [%0], [%1], 16;\n" :: "r"(s), "l"(g));
}
#define CP_COMMIT() asm volatile("cp.async.commit_group;" ::: "memory")

__device__ __forceinline__ void ldm_x4(uint32_t& r0, uint32_t& r1,
                                       uint32_t& r2, uint32_t& r3, uint32_t addr) {
    asm volatile("ldmatrix.sync.aligned.m8n8.x4.shared.b16 {%0,%1,%2,%3}, [%4];"
                 : "=r"(r0), "=r"(r1), "=r"(r2), "=r"(r3) : "r"(addr));
}

// m16n8k16 fp16 mma, fp32 accum
__device__ __forceinline__ void mma16(float* d,
                                      uint32_t a0, uint32_t a1, uint32_t a2, uint32_t a3,
                                      uint32_t b0, uint32_t b1) {
    asm volatile(
        "mma.sync.aligned.m16n8k16.row.col.f32.f16.f16.f32 "
        "{%0,%1,%2,%3}, {%4,%5,%6,%7}, {%8,%9}, {%0,%1,%2,%3};"
        : "+f"(d[0]), "+f"(d[1]), "+f"(d[2]), "+f"(d[3])
        : "r"(a0), "r"(a1), "r"(a2), "r"(a3), "r"(b0), "r"(b1));
}

// ---------------------------------------------------------------------------
// Kernel 1: per-row L2 normalize -> fp16, to scratch
// ---------------------------------------------------------------------------
__global__ void __launch_bounds__(128)
norm_kernel(const float* __restrict__ x, const float* __restrict__ w) {
    const int row = blockIdx.x;
    const float* src;
    __half* dst;
    if (row < B_DIM) {
        src = x + (size_t)row * K_DIM;
        dst = g_xn + (size_t)row * K_DIM;
    } else {
        const int r = row - B_DIM;
        src = w + (size_t)r * K_DIM;
        dst = g_wn + (size_t)r * K_DIM;
    }
    const int t = threadIdx.x;
    float4 v = reinterpret_cast<const float4*>(src)[t];
    float ss = v.x * v.x + v.y * v.y + v.z * v.z + v.w * v.w;
    #pragma unroll
    for (int o = 16; o > 0; o >>= 1) ss += __shfl_xor_sync(0xffffffffu, ss, o);
    __shared__ float red[4];
    if ((t & 31) == 0) red[t >> 5] = ss;
    __syncthreads();
    const float tot = red[0] + red[1] + red[2] + red[3];
    const float scale = 1.0f / fmaxf(sqrtf(tot), 1e-12f);
    __half2 h0 = __floats2half2_rn(v.x * scale, v.y * scale);
    __half2 h1 = __floats2half2_rn(v.z * scale, v.w * scale);
    uint2 o2 = make_uint2(*reinterpret_cast<uint32_t*>(&h0),
                          *reinterpret_cast<uint32_t*>(&h1));
    reinterpret_cast<uint2*>(dst)[t] = o2;
}

// ---------------------------------------------------------------------------
// Kernel 2: fp16 mma.sync GEMM, CTA 128x256, warp 64x64, 4-stage cp.async
// Swizzle: 16B chunk m of row r stored at slot m ^ (r & 7).
// ---------------------------------------------------------------------------
__device__ __forceinline__ void load_stage(int stage, int kc, int tid, uint32_t smem_u,
                                           const __half* __restrict__ gA,
                                           const __half* __restrict__ gB) {
    const int k0 = kc * BK;
    const uint32_t baseA = smem_u + (uint32_t)stage * STAGE_BYTES;
    const uint32_t baseB = baseA + A_STAGE_BYTES;
    #pragma unroll
    for (int i = 0; i < 4; i++) {        // A: 1024 chunks of 16B
        const int idx = tid + i * 256;
        const int r = idx >> 3, m = idx & 7;
        const uint32_t slot = (uint32_t)(m ^ (r & 7));
        cp16(baseA + (uint32_t)(r * 8 + slot) * 16u,
             gA + (size_t)r * K_DIM + k0 + m * 8);
    }
    #pragma unroll
    for (int i = 0; i < 8; i++) {        // B: 2048 chunks of 16B
        const int idx = tid + i * 256;
        const int r = idx >> 3, m = idx & 7;
        const uint32_t slot = (uint32_t)(m ^ (r & 7));
        cp16(baseB + (uint32_t)(r * 8 + slot) * 16u,
             gB + (size_t)r * K_DIM + k0 + m * 8);
    }
}

__global__ void __launch_bounds__(256, 1)
gemm_kernel(float* __restrict__ out_loss, float* __restrict__ out_pred,
            const int* __restrict__ tg) {
    extern __shared__ char dyn_smem[];
    const uint32_t smem_u = smem_u32(dyn_smem);
    const int tid = threadIdx.x;

    const int m_base = blockIdx.x * BM;    // gridDim.x = 16
    const int n_base = blockIdx.y * BN;    // gridDim.y = 125
    const __half* gA = g_xn + (size_t)m_base * K_DIM;
    const __half* gB = g_wn + (size_t)n_base * K_DIM;

    const int wid = tid >> 5;
    const int warp_m = wid & 1;            // 2 warps in M
    const int warp_n = wid >> 1;           // 4 warps in N
    const int lane = tid & 31;
    const int c = lane & 3;
    const int quad = lane >> 2;

    __shared__ int s_tg[BM];
    if (tid < BM) s_tg[tid] = tg[m_base + tid];

    float acc[4][8][4];
    #pragma unroll
    for (int t = 0; t < 4; t++)
        #pragma unroll
        for (int u = 0; u < 8; u++)
            #pragma unroll
            for (int e = 0; e < 4; e++) acc[t][u][e] = 0.0f;

    // ldmatrix lane-address components
    const int sel = lane >> 3;             // matrix index 0..3
    const int rw = lane & 7;               // row within 8x8 matrix
    // A: mat0=(m0,k0) mat1=(m+8,k0) mat2=(m0,k+8) mat3=(m+8,k+8)
    const int a_moff = (sel & 1) * 8;
    const int a_koff = sel >> 1;           // extra 16B chunk
    // B: mat0=(n0,k0) mat1=(n0,k+8) mat2=(n+8,k0) mat3=(n+8,k+8)
    const int b_noff = (sel >> 1) * 8;
    const int b_koff = sel & 1;

    // Prologue
    #pragma unroll
    for (int s = 0; s < STAGES - 1; s++) {
        load_stage(s, s, tid, smem_u, gA, gB);
        CP_COMMIT();
    }

    #pragma unroll 1
    for (int kc = 0; kc < NCHUNK; kc++) {
        asm volatile("cp.async.wait_group %0;" :: "n"(STAGES - 2));
        __syncthreads();   // stage kc visible; all warps past compute of kc-1

        const int j = kc + STAGES - 1;
        if (j < NCHUNK) load_stage(j & (STAGES - 1), j, tid, smem_u, gA, gB);
        CP_COMMIT();

        const uint32_t baseA = smem_u + (uint32_t)(kc & (STAGES - 1)) * STAGE_BYTES;
        const uint32_t baseB = baseA + A_STAGE_BYTES;

        #pragma unroll
        for (int g = 0; g < 4; g++) {      // 4 k16 groups per stage
            uint32_t bf[8][2];
            #pragma unroll
            for (int p = 0; p < 4; p++) {  // 4 n16 blocks -> 8 n8 fragments
                const int nrow = warp_n * 64 + p * 16 + b_noff + rw;
                const uint32_t slot = (uint32_t)((g * 2 + b_koff) ^ (nrow & 7));
                uint32_t r0, r1, r2, r3;
                ldm_x4(r0, r1, r2, r3, baseB + (uint32_t)nrow * 128u + slot * 16u);
                bf[2 * p][0] = r0; bf[2 * p][1] = r1;
                bf[2 * p + 1][0] = r2; bf[2 * p + 1][1] = r3;
            }
            #pragma unroll
            for (int t = 0; t < 4; t++) {
                const int mrow = warp_m * 64 + t * 16 + a_moff + rw;
                const uint32_t slot = (uint32_t)((g * 2 + a_koff) ^ (mrow & 7));
                uint32_t a0, a1, a2, a3;
                ldm_x4(a0, a1, a2, a3, baseA + (uint32_t)mrow * 128u + slot * 16u);
                #pragma unroll
                for (int u = 0; u < 8; u++)
                    mma16(acc[t][u], a0, a1, a2, a3, bf[u][0], bf[u][1]);
            }
        }
    }
    __syncthreads();

    // ---- Epilogue: regs -> SMEM (pitch 264) -> coalesced STG.128 x2 ----
    float* sE = reinterpret_cast<float*>(dyn_smem);
    #pragma unroll
    for (int t = 0; t < 4; t++) {
        const int row = warp_m * 64 + t * 16 + quad;
        #pragma unroll
        for (int u = 0; u < 8; u++) {
            const int col = warp_n * 64 + u * 8 + c * 2;
            float2 v0 = make_float2(acc[t][u][0] * 32.0f, acc[t][u][1] * 32.0f);
            float2 v1 = make_float2(acc[t][u][2] * 32.0f, acc[t][u][3] * 32.0f);
            *reinterpret_cast<float2*>(&sE[(size_t)row * 264 + col]) = v0;
            *reinterpret_cast<float2*>(&sE[(size_t)(row + 8) * 264 + col]) = v1;
        }
    }
    __syncthreads();

    #pragma unroll 4
    for (int i = 0; i < 32; i++) {
        const int linear = tid + i * 256;           // 8192 float4s total
        const int rr = linear >> 6;                 // row 0..127
        const int c4 = linear & 63;                 // float4 col 0..63
        const float4 v = *reinterpret_cast<const float4*>(&sE[(size_t)rr * 264 + c4 * 4]);
        const size_t gidx = (size_t)(m_base + rr) * C_DIM + (size_t)(n_base + c4 * 4);
        *reinterpret_cast<float4*>(&out_pred[gidx]) = v;
        // fused margin fixup on the loss copy
        float4 v2 = v;
        const int d = s_tg[rr] - (n_base + c4 * 4);
        if ((unsigned)d < 4u) reinterpret_cast<float*>(&v2)[d] -= 16.0f;
        *reinterpret_cast<float4*>(&out_loss[gidx]) = v2;
    }
}

// ---------------------------------------------------------------------------
// Launch
// ---------------------------------------------------------------------------
extern "C" void kernel_launch(void* const* d_in, const int* in_sizes, int n_in,
                              void* d_out, int out_size) {
    const float* x = (const float*)d_in[0];
    const float* w = (const float*)d_in[1];
    const int* tg = (const int*)d_in[2];

    float* out_loss = (float*)d_out;                          // tuple elem 0
    float* out_pred = out_loss + (size_t)B_DIM * C_DIM;       // tuple elem 1

    norm_kernel<<<B_DIM + C_DIM, 128>>>(x, w);

    cudaFuncSetAttribute(gemm_kernel, cudaFuncAttributeMaxDynamicSharedMemorySize,
                         DYN_SMEM);
    gemm_kernel<<<dim3(B_DIM / BM, C_DIM / BN), 256, DYN_SMEM>>>(out_loss, out_pred, tg);
}